// round 16
// baseline (speedup 1.0000x reference)
#include <cuda_runtime.h>
#include <cuda_bf16.h>
#include <cuda_fp16.h>
#include <math.h>
#include <stdint.h>

#define BATCH 8
#define SEQ   1024
#define DIM   1024
#define NHEAD 16
#define HDIM  64
#define MTOT  (BATCH*SEQ)           // 8192 tokens
#define SCALE 0.125f                // HD^-0.5
#define CAP   50.0f
#define EPSN  1e-6f
#define NEGINF (-1e30f)

// ---------------- scratch (device globals: no allocation allowed) ----------------
__device__ float g_q[MTOT*DIM];
__device__ float g_k[MTOT*DIM];
__device__ __half g_x_hi[MTOT*DIM];
__device__ __half g_att_hi[MTOT*DIM];
__device__ __half g_w_hi[4][DIM*DIM];          // q,k,v,o
__device__ __half g_qbh[MTOT*DIM];
__device__ __half g_kbh[MTOT*DIM];
__device__ __half g_vbh[MTOT*DIM];
__device__ unsigned g_maskbits[SEQ*(SEQ/32)];
__device__ int g_mask_mode;

__device__ __forceinline__ uint32_t smem_u32(const void* p) {
    uint32_t a;
    asm("{ .reg .u64 t; cvta.to.shared.u64 t, %1; cvt.u32.u64 %0, t; }" : "=r"(a) : "l"(p));
    return a;
}
__device__ __forceinline__ unsigned pk2h(__half a, __half b) {
    return (unsigned)__half_as_ushort(a) | ((unsigned)__half_as_ushort(b) << 16);
}
__device__ __forceinline__ void cp16(uint32_t s, const void* g) {
    asm volatile("cp.async.cg.shared.global [%0], [%1], 16;" :: "r"(s), "l"(g));
}
__device__ __forceinline__ void ldm_x4(uint32_t* r, uint32_t a) {
    asm volatile("ldmatrix.sync.aligned.m8n8.x4.shared.b16 {%0,%1,%2,%3}, [%4];"
        : "=r"(r[0]), "=r"(r[1]), "=r"(r[2]), "=r"(r[3]) : "r"(a));
}
__device__ __forceinline__ void ldm_x4_t(uint32_t* r, uint32_t a) {
    asm volatile("ldmatrix.sync.aligned.m8n8.x4.trans.shared.b16 {%0,%1,%2,%3}, [%4];"
        : "=r"(r[0]), "=r"(r[1]), "=r"(r[2]), "=r"(r[3]) : "r"(a));
}
__device__ __forceinline__ void mma16816h(float* c, const uint32_t* a, const uint32_t* b) {
    asm volatile("mma.sync.aligned.m16n8k16.row.col.f32.f16.f16.f32 "
        "{%0,%1,%2,%3}, {%4,%5,%6,%7}, {%8,%9}, {%0,%1,%2,%3};"
        : "+f"(c[0]), "+f"(c[1]), "+f"(c[2]), "+f"(c[3])
        : "r"(a[0]), "r"(a[1]), "r"(a[2]), "r"(a[3]), "r"(b[0]), "r"(b[1]));
}

// ---------------- mask dtype detection + packing ----------------------------------
__global__ void detect_mask_kernel(const void* m) {
    __shared__ int cu, ci, cf;
    if (threadIdx.x == 0) { cu = 0; ci = 0; cf = 0; }
    __syncthreads();
    const unsigned char* u8 = (const unsigned char*)m;
    const int*   i32 = (const int*)m;
    const float* f32 = (const float*)m;
    int lu = 0;
    for (int i = threadIdx.x; i < SEQ; i += 256)
        if (u8[(size_t)i*(SEQ+1)]) lu++;
    atomicAdd(&cu, lu);
    if (threadIdx.x < 250) {
        if (i32[(size_t)threadIdx.x*(SEQ+1)] != 0)    atomicAdd(&ci, 1);
        if (f32[(size_t)threadIdx.x*(SEQ+1)] == 1.0f) atomicAdd(&cf, 1);
    }
    __syncthreads();
    if (threadIdx.x == 0)
        g_mask_mode = (cu == SEQ) ? 0 : (cf == 250) ? 2 : (ci == 250) ? 1 : 0;
}

__global__ void pack_mask_kernel(const void* m) {
    int w = blockIdx.x * blockDim.x + threadIdx.x;
    if (w >= SEQ*SEQ/32) return;
    int mode = g_mask_mode;
    size_t base = (size_t)w * 32;
    unsigned out = 0;
    if (mode == 0) {
        const unsigned char* p = (const unsigned char*)m;
        #pragma unroll
        for (int j = 0; j < 32; j++) if (p[base+j]) out |= 1u << j;
    } else if (mode == 1) {
        const int* p = (const int*)m;
        #pragma unroll
        for (int j = 0; j < 32; j++) if (p[base+j] != 0) out |= 1u << j;
    } else {
        const float* p = (const float*)m;
        #pragma unroll
        for (int j = 0; j < 32; j++) if (p[base+j] != 0.0f) out |= 1u << j;
    }
    g_maskbits[w] = out;
}

// ---------------- fp32 -> fp16, 5 matrices (x + 4 weights; blockIdx.y selects) ----
__global__ __launch_bounds__(256) void convert_all_kernel(
    const float* x, const float* w0, const float* w1,
    const float* w2, const float* w3)
{
    int z = blockIdx.y;
    const float* src;
    __half* hi;
    int n4;
    if (z == 4) { src = x; hi = g_x_hi; n4 = MTOT*DIM/4; }
    else        { src = (z == 0) ? w0 : (z == 1) ? w1 : (z == 2) ? w2 : w3;
                  hi = g_w_hi[z]; n4 = DIM*DIM/4; }
    for (int t = blockIdx.x * 256 + threadIdx.x; t < n4; t += gridDim.x * 256) {
        float4 v = *(const float4*)(src + (size_t)t * 4);
        *(uint2*)(hi + (size_t)t * 4) = make_uint2(
            pk2h(__float2half(v.x), __float2half(v.y)),
            pk2h(__float2half(v.z), __float2half(v.w)));
    }
}

// ---------------- pure-fp16 HMMA GEMM: C = Ahi·Whi --------------------------------
// 128x128 CTA tile, 256 threads (8 warps 4x2). K=32 per stage (two k16 slices);
// ONE barrier pair per 32-K -> 32 MMAs + 12 ldmatrix between barriers.
// 2 stages x 24KB = 48KB; x2 CTAs/SM = 96KB. z==2 writes fp16 (V path).
#define GS_ROW    24
#define GS_ARR    (128*GS_ROW*2)           // 6144 B per array
#define GS_SLICE  (2*GS_ARR)               // 12288 B per k16 slice (Ahi, Bhi)
#define GS_STAGE  (2*GS_SLICE)             // 24576 B per K=32 stage
#define GS_TOTAL  (2*GS_STAGE)             // 49152 B

__global__ __launch_bounds__(256, 2) void gemm_hmma_kernel(
    const __half* __restrict__ ahi,
    const __half* w0h, float* c0,
    const __half* w1h, float* c1,
    const __half* w2h, __half* c2h)
{
    extern __shared__ char sm[];
    uint32_t sb = smem_u32(sm);
    int tid = threadIdx.x, wid = tid >> 5, lane = tid & 31;
    int bn0 = blockIdx.x * 128, bm0 = blockIdx.y * 128, z = blockIdx.z;
    const __half* wh = (z == 0) ? w0h : (z == 1) ? w1h : w2h;

    int wm = wid >> 1, wn = wid & 1;

    int lrow = tid >> 1, lhalf = tid & 1;
    const __half* gA_hi = ahi + (size_t)(bm0 + lrow) * DIM + lhalf * 8;
    const __half* gB_hi = wh  + (size_t)(bn0 + lrow) * DIM + lhalf * 8;
    uint32_t sOff = (uint32_t)(lrow * GS_ROW + lhalf * 8) * 2;

    float acc[2][8][4];
    #pragma unroll
    for (int i = 0; i < 2; i++)
        #pragma unroll
        for (int j = 0; j < 8; j++)
            #pragma unroll
            for (int r = 0; r < 4; r++) acc[i][j][r] = 0.0f;

    uint32_t aRowByte = (uint32_t)((wm*32 + (lane & 15)) * GS_ROW + (lane >> 4) * 8) * 2;
    uint32_t bRowByte = (uint32_t)((wn*64 + ((lane >> 4) & 1)*8 + (lane & 7)) * GS_ROW
                                   + ((lane >> 3) & 1) * 8) * 2;

    // stage loader: K=32 = two k16 slices, one cp.async group (4 cp16/thread)
    auto load_stage = [&](int st) {
        uint32_t s0 = sb + (uint32_t)(st & 1) * GS_STAGE + sOff;
        #pragma unroll
        for (int sub = 0; sub < 2; sub++) {
            int k0 = st * 32 + sub * 16;
            uint32_t sp = s0 + (uint32_t)sub * GS_SLICE;
            cp16(sp,          gA_hi + k0);
            cp16(sp + GS_ARR, gB_hi + k0);
        }
        asm volatile("cp.async.commit_group;");
    };

    load_stage(0);

    for (int st = 0; st < 32; st++) {
        int cur = st & 1;
        if (st < 31) {
            load_stage(st + 1);
            asm volatile("cp.async.wait_group 1;");
        } else {
            asm volatile("cp.async.wait_group 0;");
        }
        __syncthreads();

        #pragma unroll
        for (int sub = 0; sub < 2; sub++) {
            uint32_t bufb = sb + (uint32_t)cur * GS_STAGE + (uint32_t)sub * GS_SLICE;
            uint32_t ah[2][4];
            #pragma unroll
            for (int mf = 0; mf < 2; mf++)
                ldm_x4(ah[mf], bufb + aRowByte + (uint32_t)(mf * 16 * GS_ROW) * 2);
            #pragma unroll
            for (int pr = 0; pr < 4; pr++) {
                uint32_t bhv[4];
                ldm_x4(bhv, bufb + GS_ARR + bRowByte + (uint32_t)(pr * 16 * GS_ROW) * 2);
                #pragma unroll
                for (int mf = 0; mf < 2; mf++) {
                    mma16816h(acc[mf][2*pr],   ah[mf], bhv);
                    mma16816h(acc[mf][2*pr+1], ah[mf], bhv+2);
                }
            }
        }
        __syncthreads();
    }

    int gid4 = lane >> 2, l4 = lane & 3;
    if (z == 2) {
        // V projection: write fp16 directly for the attention kernel
        #pragma unroll
        for (int mf = 0; mf < 2; mf++) {
            int row = bm0 + wm*32 + mf*16 + gid4;
            #pragma unroll
            for (int nf = 0; nf < 8; nf++) {
                int col = bn0 + wn*64 + nf*8 + l4*2;
                *(uint32_t*)(c2h + (size_t)row * DIM + col) =
                    pk2h(__float2half(acc[mf][nf][0]), __float2half(acc[mf][nf][1]));
                *(uint32_t*)(c2h + (size_t)(row + 8) * DIM + col) =
                    pk2h(__float2half(acc[mf][nf][2]), __float2half(acc[mf][nf][3]));
            }
        }
    } else {
        float* C = (z == 0) ? c0 : c1;
        #pragma unroll
        for (int mf = 0; mf < 2; mf++) {
            int row = bm0 + wm*32 + mf*16 + gid4;
            #pragma unroll
            for (int nf = 0; nf < 8; nf++) {
                int col = bn0 + wn*64 + nf*8 + l4*2;
                *(float2*)(C + (size_t)row * DIM + col) =
                    make_float2(acc[mf][nf][0], acc[mf][nf][1]);
                *(float2*)(C + (size_t)(row + 8) * DIM + col) =
                    make_float2(acc[mf][nf][2], acc[mf][nf][3]);
            }
        }
    }
}

// ---------------- QKNorm + RoPE -> fp16 (Q and K) ---------------------------------
__global__ __launch_bounds__(256) void norm_rope_kernel(
    const float* __restrict__ qg, const float* __restrict__ kg,
    const float* __restrict__ cosb, const float* __restrict__ sinb,
    const int* __restrict__ ridx)
{
    int task = blockIdx.x * 8 + (threadIdx.x >> 5);
    int t = threadIdx.x & 31;
    int which = task >> 17;
    int rem = task & 0x1FFFF;
    int head = rem & (NHEAD - 1);
    int tok  = rem >> 4;
    const float* base = (which ? g_k : g_q) + (size_t)tok * DIM + head * HDIM;
    const float* gamma = which ? kg : qg;
    float x0 = base[t], x1 = base[t + 32];
    float ss = x0*x0 + x1*x1;
    #pragma unroll
    for (int off = 16; off >= 1; off >>= 1)
        ss += __shfl_xor_sync(0xffffffffu, ss, off);
    float r = rsqrtf(ss * (1.0f/64.0f) + EPSN);
    float n0 = x0 * r * gamma[t];
    float n1 = x1 * r * gamma[t + 32];
    int idx = ridx[tok & (SEQ - 1)];
    if (idx >= 0) {
        const float* cp = cosb + (size_t)idx * HDIM;
        const float* sp = sinb + (size_t)idx * HDIM;
        float o0 = n0 * cp[t]      - n1 * sp[t];
        float o1 = n1 * cp[t + 32] + n0 * sp[t + 32];
        n0 = o0; n1 = o1;
    }
    __half* dh = (which ? g_kbh : g_qbh) + (size_t)tok * DIM + head * HDIM;
    dh[t]      = __float2half(n0);
    dh[t + 32] = __float2half(n1);
}

// ---------------- tensor-core flash attention, pure fp16 (R15, passed) ------------
#define A_STR   144
#define A_QH    0
#define A_ST0   (128*A_STR)                 // 18432
#define A_KH    0
#define A_VH    18432
#define A_STAGE 36864
#define A_SMEM  (A_ST0 + 2*A_STAGE)         // 92160

__global__ __launch_bounds__(256, 1) void attn_tc_kernel() {
    extern __shared__ char smc[];
    uint32_t sb = smem_u32(smc);
    int tid = threadIdx.x, wid = tid >> 5, lane = tid & 31;
    int qt = blockIdx.x, h = blockIdx.y, b = blockIdx.z;
    int gid4 = lane >> 2, l4 = lane & 3;

    size_t qtok0 = (size_t)(b*SEQ + qt*128);

    #pragma unroll
    for (int i = 0; i < 4; i++) {
        int id = tid + i*256;
        int r = id >> 3, ch = id & 7;
        size_t gq = (qtok0 + r) * DIM + h*HDIM + ch*8;
        cp16(sb + A_QH + r*A_STR + ch*16, g_qbh + gq);
        size_t gk = ((size_t)(b*SEQ + r)) * DIM + h*HDIM + ch*8;
        uint32_t st = sb + A_ST0;
        cp16(st + A_KH + r*A_STR + ch*16, g_kbh + gk);
        cp16(st + A_VH + r*A_STR + ch*16, g_vbh + gk);
    }
    asm volatile("cp.async.commit_group;");
    asm volatile("cp.async.wait_group 0;");
    __syncthreads();

    uint32_t qfh[4][4];
    {
        uint32_t arow = (uint32_t)(wid*16 + (lane & 15));
        uint32_t acol = (uint32_t)((lane >> 4) * 16);
        #pragma unroll
        for (int ks = 0; ks < 4; ks++)
            ldm_x4(qfh[ks], sb + A_QH + arow*A_STR + ks*32 + acol);
    }

    float o[8][4];
    #pragma unroll
    for (int i = 0; i < 8; i++)
        #pragma unroll
        for (int j = 0; j < 4; j++) o[i][j] = 0.0f;
    float m0 = NEGINF, m1 = NEGINF, l0 = 0.0f, l1 = 0.0f;

    int qr0 = qt*128 + wid*16 + gid4;
    uint32_t brow = (uint32_t)(((lane >> 4) & 1)*8 + (lane & 7));
    uint32_t bcol = (uint32_t)(((lane >> 3) & 1) * 16);
    uint32_t vrow = (uint32_t)(((lane >> 3) & 1)*8 + (lane & 7));
    uint32_t vcol = (uint32_t)((lane >> 4) * 16);

    for (int kt = 0; kt < 8; kt++) {
        uint32_t st = sb + A_ST0 + (uint32_t)(kt & 1)*A_STAGE;
        if (kt < 7) {
            uint32_t sn = sb + A_ST0 + (uint32_t)((kt+1) & 1)*A_STAGE;
            #pragma unroll
            for (int i = 0; i < 4; i++) {
                int id = tid + i*256;
                int r = id >> 3, ch = id & 7;
                size_t g = ((size_t)(b*SEQ + (kt+1)*128 + r)) * DIM + h*HDIM + ch*8;
                cp16(sn + A_KH + r*A_STR + ch*16, g_kbh + g);
                cp16(sn + A_VH + r*A_STR + ch*16, g_vbh + g);
            }
            asm volatile("cp.async.commit_group;");
            asm volatile("cp.async.wait_group 1;");
        } else {
            asm volatile("cp.async.wait_group 0;");
        }
        __syncthreads();

        // ---- S = Qhi Khi^T ----
        float c[16][4];
        #pragma unroll
        for (int i = 0; i < 16; i++)
            #pragma unroll
            for (int j = 0; j < 4; j++) c[i][j] = 0.0f;
        #pragma unroll
        for (int ks = 0; ks < 4; ks++) {
            #pragma unroll
            for (int np = 0; np < 8; np++) {
                uint32_t kb[4];
                uint32_t off = (uint32_t)(np*16 + brow)*A_STR + ks*32 + bcol;
                ldm_x4(kb, st + A_KH + off);
                mma16816h(c[2*np],   qfh[ks], kb);
                mma16816h(c[2*np+1], qfh[ks], kb+2);
            }
        }

        unsigned w0[4], w1[4];
        #pragma unroll
        for (int w = 0; w < 4; w++) {
            w0[w] = g_maskbits[qr0*32 + kt*4 + w];
            w1[w] = g_maskbits[(qr0+8)*32 + kt*4 + w];
        }
        float tm0 = NEGINF, tm1 = NEGINF;
        #pragma unroll
        for (int nf = 0; nf < 16; nf++) {
            int word = nf >> 2;
            int bit = (nf & 3)*8 + l4*2;
            #pragma unroll
            for (int e = 0; e < 4; e++) {
                float y  = c[nf][e] * (SCALE / CAP);
                float y2 = y * y;
                float a  = CAP * (y * (1.0f + y2 * (-0.3333333433f + y2 * 0.1333333403f)));
                unsigned wv = (e < 2) ? w0[word] : w1[word];
                c[nf][e] = ((wv >> (bit + (e & 1))) & 1u) ? a : NEGINF;
            }
            tm0 = fmaxf(tm0, fmaxf(c[nf][0], c[nf][1]));
            tm1 = fmaxf(tm1, fmaxf(c[nf][2], c[nf][3]));
        }
        tm0 = fmaxf(tm0, __shfl_xor_sync(0xffffffffu, tm0, 1));
        tm0 = fmaxf(tm0, __shfl_xor_sync(0xffffffffu, tm0, 2));
        tm1 = fmaxf(tm1, __shfl_xor_sync(0xffffffffu, tm1, 1));
        tm1 = fmaxf(tm1, __shfl_xor_sync(0xffffffffu, tm1, 2));
        float mn0 = fmaxf(m0, tm0), mn1 = fmaxf(m1, tm1);
        float al0 = __expf(m0 - mn0), al1 = __expf(m1 - mn1);
        m0 = mn0; m1 = mn1;
        float rs0 = 0.0f, rs1 = 0.0f;
        #pragma unroll
        for (int nf = 0; nf < 16; nf++) {
            c[nf][0] = __expf(c[nf][0] - mn0);
            c[nf][1] = __expf(c[nf][1] - mn0);
            c[nf][2] = __expf(c[nf][2] - mn1);
            c[nf][3] = __expf(c[nf][3] - mn1);
            rs0 += c[nf][0] + c[nf][1];
            rs1 += c[nf][2] + c[nf][3];
        }
        rs0 += __shfl_xor_sync(0xffffffffu, rs0, 1);
        rs0 += __shfl_xor_sync(0xffffffffu, rs0, 2);
        rs1 += __shfl_xor_sync(0xffffffffu, rs1, 1);
        rs1 += __shfl_xor_sync(0xffffffffu, rs1, 2);
        l0 = l0 * al0 + rs0;
        l1 = l1 * al1 + rs1;
        #pragma unroll
        for (int nf = 0; nf < 8; nf++) {
            o[nf][0] *= al0; o[nf][1] *= al0; o[nf][2] *= al1; o[nf][3] *= al1;
        }

        // ---- O += Phi Vhi ----
        #pragma unroll
        for (int ks = 0; ks < 8; ks++) {
            uint32_t pah[4];
            pah[0] = pk2h(__float2half(c[2*ks][0]),   __float2half(c[2*ks][1]));
            pah[1] = pk2h(__float2half(c[2*ks][2]),   __float2half(c[2*ks][3]));
            pah[2] = pk2h(__float2half(c[2*ks+1][0]), __float2half(c[2*ks+1][1]));
            pah[3] = pk2h(__float2half(c[2*ks+1][2]), __float2half(c[2*ks+1][3]));
            #pragma unroll
            for (int npv = 0; npv < 4; npv++) {
                uint32_t vb[4];
                uint32_t off = (uint32_t)(ks*16 + vrow)*A_STR + npv*32 + vcol;
                ldm_x4_t(vb, st + A_VH + off);
                mma16816h(o[2*npv],   pah, vb);
                mma16816h(o[2*npv+1], pah, vb+2);
            }
        }
        __syncthreads();
    }

    // epilogue: normalize, write fp16 for the O projection
    float inv0 = 1.0f / l0, inv1 = 1.0f / l1;
    size_t r0g = (qtok0 + wid*16 + gid4) * DIM + h*HDIM;
    size_t r1g = r0g + (size_t)8 * DIM;
    #pragma unroll
    for (int nf = 0; nf < 8; nf++) {
        int col = nf*8 + l4*2;
        *(uint32_t*)(g_att_hi + r0g + col) =
            pk2h(__float2half(o[nf][0]*inv0), __float2half(o[nf][1]*inv0));
        *(uint32_t*)(g_att_hi + r1g + col) =
            pk2h(__float2half(o[nf][2]*inv1), __float2half(o[nf][3]*inv1));
    }
}

// ---------------- launch ----------------------------------------------------------
extern "C" void kernel_launch(void* const* d_in, const int* in_sizes, int n_in,
                              void* d_out, int out_size)
{
    const float* x    = (const float*)d_in[0];
    const float* Wq   = (const float*)d_in[1];
    const float* Wk   = (const float*)d_in[2];
    const float* Wv   = (const float*)d_in[3];
    const float* Wo   = (const float*)d_in[4];
    const float* qg   = (const float*)d_in[5];
    const float* kg   = (const float*)d_in[6];
    const float* cosb = (const float*)d_in[7];
    const float* sinb = (const float*)d_in[8];
    const int*   ridx = (const int*)d_in[9];
    const void*  mask = d_in[10];
    float* out = (float*)d_out;

    float *gq, *gk;
    __half *xhi, *athi, *whB, *vbh;
    cudaGetSymbolAddress((void**)&gq,   g_q);
    cudaGetSymbolAddress((void**)&gk,   g_k);
    cudaGetSymbolAddress((void**)&xhi,  g_x_hi);
    cudaGetSymbolAddress((void**)&athi, g_att_hi);
    cudaGetSymbolAddress((void**)&whB,  g_w_hi);
    cudaGetSymbolAddress((void**)&vbh,  g_vbh);
    __half *wqh = whB;
    __half *wkh = whB + 1*DIM*DIM;
    __half *wvh = whB + 2*DIM*DIM;
    __half *woh = whB + 3*DIM*DIM;

    cudaFuncSetAttribute(gemm_hmma_kernel,
        cudaFuncAttributeMaxDynamicSharedMemorySize, GS_TOTAL);
    cudaFuncSetAttribute(attn_tc_kernel,
        cudaFuncAttributeMaxDynamicSharedMemorySize, A_SMEM);

    // QKV GEMM kept at an early launch position for ncu capture (now 3rd/4th).
    detect_mask_kernel<<<1, 256>>>(mask);                                            // 1
    convert_all_kernel<<<dim3(1024, 5), 256>>>(x, Wq, Wk, Wv, Wo);                   // 2

    gemm_hmma_kernel<<<dim3(8, 64, 3), 256, GS_TOTAL>>>(                             // 3 (QKV; V->fp16)
        xhi, wqh, gq, wkh, gk, wvh, vbh);

    pack_mask_kernel<<<(SEQ*SEQ/32 + 255)/256, 256>>>(mask);                         // 4
    norm_rope_kernel<<<(2*MTOT*NHEAD)/8, 256>>>(qg, kg, cosb, sinb, ridx);           // 5

    attn_tc_kernel<<<dim3(SEQ/128, NHEAD, BATCH), 256, A_SMEM>>>();                  // 6

    gemm_hmma_kernel<<<dim3(8, 64, 1), 256, GS_TOTAL>>>(                             // 7 (O)
        athi, woh, out, woh, out, woh, (half*)out /*unused*/);
}